// round 10
// baseline (speedup 1.0000x reference)
#include <cuda_runtime.h>
#include <math.h>

// Problem: input (8, 64, 64, 3) fp32 -> scalar fp32.
#define NB   8
#define NPIX 4096            // 64*64
#define NELE (NB * NPIX)     // 32768
#define NBLK 576             // triangular block set (see c_off)
#define PREB 64              // blocks that also run the pre-phase

// ---- scratch (no allocations allowed -> __device__ globals) ----
__device__ __align__(16) float g_a[NELE];        // |x|.sum(-1), layout [b][i]
__device__ __align__(16) float g_t[NELE];        // same values, pixel-major [i][b]
__device__ float        g_bmin[PREB];
__device__ float        g_bmax[PREB];
__device__ float        g_inv, g_nb;             // f = fma(a, inv, nb)
__device__ double       g_part[NBLK];
__device__ unsigned int g_cnt_pre  = 0;          // all self-resetting per launch
__device__ unsigned int g_cnt_main = 0;
__device__ unsigned int g_ready    = 0;

// i-tile = 8 rows (bx 0..7); per bx: jy in [8bx, 64), 2 chunks of 32 j each.
__constant__ int c_off[9] = {0, 128, 240, 336, 416, 480, 528, 560, 576};

// ---- packed f32x2 helpers (Blackwell FFMA2 — only reachable via PTX) ----
__device__ __forceinline__ unsigned long long pk2(float lo, float hi) {
    unsigned long long r;
    asm("mov.b64 %0, {%1,%2};" : "=l"(r) : "f"(lo), "f"(hi));
    return r;
}
__device__ __forceinline__ void unpk2(unsigned long long v, float& lo, float& hi) {
    asm("mov.b64 {%0,%1}, %2;" : "=f"(lo), "=f"(hi) : "l"(v));
}
__device__ __forceinline__ unsigned long long mul2(unsigned long long a, unsigned long long b) {
    unsigned long long r;
    asm("mul.rn.f32x2 %0, %1, %2;" : "=l"(r) : "l"(a), "l"(b));
    return r;
}
__device__ __forceinline__ unsigned long long fma2(unsigned long long a, unsigned long long b,
                                                   unsigned long long c) {
    unsigned long long r;
    asm("fma.rn.f32x2 %0, %1, %2, %3;" : "=l"(r) : "l"(a), "l"(b), "l"(c));
    return r;
}

// ---------------------------------------------------------------
// ONE kernel. Blocks 0..63: pre-phase (abs-sum, transpose, min/max) then main.
// All blocks: build sqrt table while pre-phase runs, spin on g_ready, then the
// weighted symmetric pair sum. Block = (8 i-rows) x (32-j chunk), 2 px/thread.
__global__ void __launch_bounds__(256) k_fused(const float4* __restrict__ in4,
                                               float* __restrict__ out) {
    __shared__ __align__(8)  float2 s_d2[512];     // [r 0..3][m 0..127] weighted dist
    __shared__ __align__(16) float  s_fj[256];     // 32 j x 8 b, pixel-major
    __shared__ float  s_mm[8];
    __shared__ double s_red[8];
    __shared__ bool   s_flag;

    int tid  = threadIdx.x;
    int lane = tid & 31, wid = tid >> 5;
    int bid  = blockIdx.x;

    // ---- decode (bx, jy, jlo) ----
    int bx = 0;
    #pragma unroll
    for (int t = 1; t < 8; t++) bx += (bid >= c_off[t]);
    int rel = bid - c_off[bx];
    int jy  = 8 * bx + (rel >> 1);
    int jlo = (rel & 1) << 5;
    int ry0 = bx * 8;

    // ================= PRE PHASE (blocks 0..63) =================
    if (bid < PREB) {
        float mn = 1e30f, mx = -1e30f;
        if (tid < 128) {
            int t = bid * 128 + tid;                   // 0..8191
            float4 a = in4[t * 3 + 0];
            float4 b = in4[t * 3 + 1];
            float4 c = in4[t * 3 + 2];
            float4 s;
            s.x = fabsf(a.x) + fabsf(a.y) + fabsf(a.z);
            s.y = fabsf(a.w) + fabsf(b.x) + fabsf(b.y);
            s.z = fabsf(b.z) + fabsf(b.w) + fabsf(c.x);
            s.w = fabsf(c.y) + fabsf(c.z) + fabsf(c.w);
            *(float4*)&g_a[t * 4] = s;

            int bb = t >> 10;                          // batch
            int p0 = (t & 1023) * 4;                   // first pixel
            g_t[(p0 + 0) * 8 + bb] = s.x;
            g_t[(p0 + 1) * 8 + bb] = s.y;
            g_t[(p0 + 2) * 8 + bb] = s.z;
            g_t[(p0 + 3) * 8 + bb] = s.w;

            mn = fminf(fminf(s.x, s.y), fminf(s.z, s.w));
            mx = fmaxf(fmaxf(s.x, s.y), fmaxf(s.z, s.w));
            #pragma unroll
            for (int o = 16; o; o >>= 1) {
                mn = fminf(mn, __shfl_xor_sync(0xffffffffu, mn, o));
                mx = fmaxf(mx, __shfl_xor_sync(0xffffffffu, mx, o));
            }
            if (lane == 0) { s_mm[wid] = mn; s_mm[4 + wid] = mx; }
        }
        __syncthreads();
        if (tid == 0) {
            mn = fminf(fminf(s_mm[0], s_mm[1]), fminf(s_mm[2], s_mm[3]));
            mx = fmaxf(fmaxf(s_mm[4], s_mm[5]), fmaxf(s_mm[6], s_mm[7]));
            g_bmin[bid] = mn;
            g_bmax[bid] = mx;
            __threadfence();
            s_flag = (atomicAdd(&g_cnt_pre, 1u) == PREB - 1u);
        }
        __syncthreads();
        if (s_flag) {                                  // last pre-block finishes
            if (tid < 64) {
                float m2 = ((volatile float*)g_bmin)[tid];
                float x2 = ((volatile float*)g_bmax)[tid];
                #pragma unroll
                for (int o = 16; o; o >>= 1) {
                    m2 = fminf(m2, __shfl_xor_sync(0xffffffffu, m2, o));
                    x2 = fmaxf(x2, __shfl_xor_sync(0xffffffffu, x2, o));
                }
                if (lane == 0) { s_mm[wid] = m2; s_mm[4 + wid] = x2; }
            }
            __syncthreads();
            if (tid == 0) {
                float mnF = fminf(s_mm[0], s_mm[1]);
                float mxF = fmaxf(s_mm[4], s_mm[5]);
                float inv = 1.0f / (mxF - mnF);
                g_inv = inv;
                g_nb  = -mnF * inv;
                g_cnt_pre = 0;                         // reset for graph replay
                __threadfence();
                atomicExch(&g_ready, 1u);
            }
        }
    }

    // ====== data-independent work overlaps pre-phase / spin ======
    // weighted signed-index distance table: 2 float2 entries/thread
    #pragma unroll
    for (int e = tid; e < 512; e += 256) {
        int r  = e >> 7;                               // local row 0..3 (pairs r, r+4)
        int m  = e & 127;
        int dx = m - 63;                               // ix - jx
        int dy0 = jy - (ry0 + r);
        int dy1 = dy0 - 4;
        float w0 = (dy0 > 0) ? 2.0f : (dy0 == 0 ? 1.0f : 0.0f);
        float w1 = (dy1 > 0) ? 2.0f : (dy1 == 0 ? 1.0f : 0.0f);
        float2 d;
        d.x = w0 * sqrtf((float)(dy0 * dy0 + dx * dx));
        d.y = w1 * sqrtf((float)(dy1 * dy1 + dx * dx));
        s_d2[e] = d;
    }

    // ---- wait for pre-phase (L2 atomic poll by one thread) ----
    if (tid == 0) {
        while (atomicAdd(&g_ready, 0u) == 0u) { }
    }
    __syncthreads();

    float inv = __ldcg(&g_inv);
    float nb  = __ldcg(&g_nb);

    // normalized f of the 32-j chunk (coalesced, L2-coherent loads)
    {
        int b = tid >> 5, x = tid & 31;
        s_fj[x * 8 + b] = fmaf(__ldcg(&g_a[b * NPIX + jy * 64 + jlo + x]), inv, nb);
    }

    // this thread's two pixels from the pixel-major mirror
    int iA = bx * 512 + tid;
    unsigned long long fA[4], fB[4];
    {
        float4 lo  = __ldcg((const float4*)&g_t[iA * 8]);
        float4 hi  = __ldcg((const float4*)&g_t[iA * 8 + 4]);
        float4 lo2 = __ldcg((const float4*)&g_t[(iA + 256) * 8]);
        float4 hi2 = __ldcg((const float4*)&g_t[(iA + 256) * 8 + 4]);
        fA[0] = pk2(fmaf(lo.x,  inv, nb), fmaf(lo.y,  inv, nb));
        fA[1] = pk2(fmaf(lo.z,  inv, nb), fmaf(lo.w,  inv, nb));
        fA[2] = pk2(fmaf(hi.x,  inv, nb), fmaf(hi.y,  inv, nb));
        fA[3] = pk2(fmaf(hi.z,  inv, nb), fmaf(hi.w,  inv, nb));
        fB[0] = pk2(fmaf(lo2.x, inv, nb), fmaf(lo2.y, inv, nb));
        fB[1] = pk2(fmaf(lo2.z, inv, nb), fmaf(lo2.w, inv, nb));
        fB[2] = pk2(fmaf(hi2.x, inv, nb), fmaf(hi2.y, inv, nb));
        fB[3] = pk2(fmaf(hi2.z, inv, nb), fmaf(hi2.w, inv, nb));
    }
    __syncthreads();

    // ---- inner loop: 32 j, 2 pixels/thread ----
    int ix = tid & 63;
    const float2* dbase = s_d2 + ((tid >> 6) << 7) + (ix - jlo + 63);

    unsigned long long acc0 = 0ull, acc1 = 0ull;
    #pragma unroll 16
    for (int jj = 0; jj < 32; jj++) {
        ulonglong2 ja = *(const ulonglong2*)(s_fj + jj * 8);      // b 0..3
        ulonglong2 jb = *(const ulonglong2*)(s_fj + jj * 8 + 4);  // b 4..7
        float2 d = dbase[-jj];                          // LDS.64, imm offset

        unsigned long long p = mul2(fA[0], ja.x);       // lanes: even/odd batches
        p = fma2(fA[1], ja.y, p);
        p = fma2(fA[2], jb.x, p);
        p = fma2(fA[3], jb.y, p);
        acc0 = fma2(p, pk2(d.x, d.x), acc0);

        unsigned long long q = mul2(fB[0], ja.x);
        q = fma2(fB[1], ja.y, q);
        q = fma2(fB[2], jb.x, q);
        q = fma2(fB[3], jb.y, q);
        acc1 = fma2(q, pk2(d.y, d.y), acc1);
    }

    // ---- block reduce (double) ----
    float a0, a1, b0, b1;
    unpk2(acc0, a0, a1);
    unpk2(acc1, b0, b1);
    double dacc = ((double)a0 + (double)a1) + ((double)b0 + (double)b1);
    #pragma unroll
    for (int o = 16; o; o >>= 1)
        dacc += __shfl_xor_sync(0xffffffffu, dacc, o);
    if (lane == 0) s_red[wid] = dacc;
    __syncthreads();
    if (tid == 0) {
        double s = s_red[0];
        #pragma unroll
        for (int w = 1; w < 8; w++) s += s_red[w];
        g_part[bid] = s;
        __threadfence();
        s_flag = (atomicAdd(&g_cnt_main, 1u) == NBLK - 1u);
    }
    __syncthreads();

    // ---- last block reduces all partials (fixed order -> deterministic) ----
    if (s_flag) {
        double s = 0.0;
        for (int k = tid; k < NBLK; k += 256)
            s += ((volatile double*)g_part)[k];
        #pragma unroll
        for (int o = 16; o; o >>= 1)
            s += __shfl_xor_sync(0xffffffffu, s, o);
        if (lane == 0) s_red[wid] = s;
        __syncthreads();
        if (tid == 0) {
            double t = s_red[0];
            #pragma unroll
            for (int w = 1; w < 8; w++) t += s_red[w];
            out[0] = (float)(t / 134217728.0);          // / (B*N*N)
            g_cnt_main = 0;                             // reset for graph replay
            g_ready    = 0;
        }
    }
}

extern "C" void kernel_launch(void* const* d_in, const int* in_sizes, int n_in,
                              void* d_out, int out_size) {
    const float4* in4 = (const float4*)d_in[0];
    float*        out = (float*)d_out;
    k_fused<<<NBLK, 256>>>(in4, out);
}

// round 11
// speedup vs baseline: 1.0485x; 1.0485x over previous
#include <cuda_runtime.h>
#include <math.h>

// Problem: input (8, 64, 64, 3) fp32 -> scalar fp32.
#define NB   8
#define NPIX 4096            // 64*64
#define NELE (NB * NPIX)     // 32768
#define PRE_BLKS 64
#define MAIN_BLKS 288        // triangular block set (see c_off)

// ---- scratch (no allocations allowed -> __device__ globals) ----
__device__ __align__(16) float g_a[NELE];        // |x|.sum(-1), layout [b][i]
__device__ __align__(16) float g_t[NELE];        // same values, pixel-major [i][b]
__device__ float        g_bmin[PRE_BLKS];
__device__ float        g_bmax[PRE_BLKS];
__device__ float        g_inv, g_nb;             // f = fma(a, inv, nb)
__device__ double       g_part[MAIN_BLKS];
__device__ unsigned int g_cnt_pre  = 0;          // self-resetting counters
__device__ unsigned int g_cnt_main = 0;

// i-tile = 8 rows (bx 0..7). For each bx, jy in [8bx, 64) -> 64-8bx blocks.
__constant__ int c_off[9] = {0, 64, 120, 168, 208, 240, 264, 280, 288};

// ---- packed f32x2 helpers (Blackwell FFMA2 — only reachable via PTX) ----
__device__ __forceinline__ unsigned long long pk2(float lo, float hi) {
    unsigned long long r;
    asm("mov.b64 %0, {%1,%2};" : "=l"(r) : "f"(lo), "f"(hi));
    return r;
}
__device__ __forceinline__ void unpk2(unsigned long long v, float& lo, float& hi) {
    asm("mov.b64 {%0,%1}, %2;" : "=f"(lo), "=f"(hi) : "l"(v));
}
__device__ __forceinline__ unsigned long long mul2(unsigned long long a, unsigned long long b) {
    unsigned long long r;
    asm("mul.rn.f32x2 %0, %1, %2;" : "=l"(r) : "l"(a), "l"(b));
    return r;
}
__device__ __forceinline__ unsigned long long fma2(unsigned long long a, unsigned long long b,
                                                   unsigned long long c) {
    unsigned long long r;
    asm("fma.rn.f32x2 %0, %1, %2, %3;" : "=l"(r) : "l"(a), "l"(b), "l"(c));
    return r;
}

// ---------------------------------------------------------------
// 4 pixels/thread (3 x LDG.128). Writes g_a (batch-major), g_t (pixel-major),
// per-block min/max; last block finishes min/max and publishes (inv, nb).
__global__ void __launch_bounds__(128) k_pre(const float4* __restrict__ in4) {
    int t = blockIdx.x * 128 + threadIdx.x;            // 0..8191
    float4 a = in4[t * 3 + 0];
    float4 b = in4[t * 3 + 1];
    float4 c = in4[t * 3 + 2];

    float4 s;
    s.x = fabsf(a.x) + fabsf(a.y) + fabsf(a.z);
    s.y = fabsf(a.w) + fabsf(b.x) + fabsf(b.y);
    s.z = fabsf(b.z) + fabsf(b.w) + fabsf(c.x);
    s.w = fabsf(c.y) + fabsf(c.z) + fabsf(c.w);
    *(float4*)&g_a[t * 4] = s;

    int bb = t >> 10;                                  // batch
    int p0 = (t & 1023) * 4;                           // first pixel
    g_t[(p0 + 0) * 8 + bb] = s.x;
    g_t[(p0 + 1) * 8 + bb] = s.y;
    g_t[(p0 + 2) * 8 + bb] = s.z;
    g_t[(p0 + 3) * 8 + bb] = s.w;

    float mn = fminf(fminf(s.x, s.y), fminf(s.z, s.w));
    float mx = fmaxf(fmaxf(s.x, s.y), fmaxf(s.z, s.w));
    #pragma unroll
    for (int o = 16; o; o >>= 1) {
        mn = fminf(mn, __shfl_xor_sync(0xffffffffu, mn, o));
        mx = fmaxf(mx, __shfl_xor_sync(0xffffffffu, mx, o));
    }
    __shared__ float smn[4], smx[4];
    __shared__ bool  s_last;
    int wid = threadIdx.x >> 5, lid = threadIdx.x & 31;
    if (lid == 0) { smn[wid] = mn; smx[wid] = mx; }
    __syncthreads();
    if (threadIdx.x == 0) {
        #pragma unroll
        for (int w = 1; w < 4; w++) { mn = fminf(mn, smn[w]); mx = fmaxf(mx, smx[w]); }
        g_bmin[blockIdx.x] = mn;
        g_bmax[blockIdx.x] = mx;
        __threadfence();
        s_last = (atomicAdd(&g_cnt_pre, 1u) == PRE_BLKS - 1u);
    }
    __syncthreads();
    if (s_last) {
        if (threadIdx.x < 64) {
            float m2 = ((volatile float*)g_bmin)[threadIdx.x];
            float x2 = ((volatile float*)g_bmax)[threadIdx.x];
            #pragma unroll
            for (int o = 16; o; o >>= 1) {
                m2 = fminf(m2, __shfl_xor_sync(0xffffffffu, m2, o));
                x2 = fmaxf(x2, __shfl_xor_sync(0xffffffffu, x2, o));
            }
            if (threadIdx.x == 0)  { smn[0] = m2; smx[1] = x2; }
            if (threadIdx.x == 32) { smx[0] = x2; smn[1] = m2; }
        }
        __syncthreads();
        if (threadIdx.x == 0) {
            float mnF = fminf(smn[0], smn[1]);
            float mxF = fmaxf(smx[0], smx[1]);
            float inv = 1.0f / (mxF - mnF);
            g_inv = inv;
            g_nb  = -mnF * inv;
            g_cnt_pre = 0;                              // reset for graph replay
        }
    }
}

// ---------------------------------------------------------------
// Symmetric main kernel. Block = (i-tile of 8 rows = 512 px) x (full j-row).
// Only jy >= ry0 launched; pair weight {0,1,2} folded into the lane-duplicated
// signed-index distance table s_d4[r][ix - jx + 63] = (d0,d0,d1,d1) for local
// rows r and r+4. Thread: iA = tile+tid (row r = tid>>6), iB = iA+256 (r+4).
// min-blocks=2 frees the register budget (128) so ptxas can software-pipeline
// the unrolled LDS + FFMA2 stream (38-reg version exposed full LDS latency).
__global__ void __launch_bounds__(256, 2) k_main(float* __restrict__ out) {
    __shared__ __align__(16) float4 s_d4[512];         // [r 0..3][m 0..127]
    __shared__ __align__(16) float  s_fj[512];         // 64 j x 8 b, pixel-major
    __shared__ double s_red[8];
    __shared__ bool   s_last;

    int tid  = threadIdx.x;
    int lane = tid & 31, wid = tid >> 5;

    // ---- decode (bx, jy) ----
    int bid = blockIdx.x;
    int bx = 0;
    #pragma unroll
    for (int t = 1; t < 8; t++) bx += (bid >= c_off[t]);
    int jy  = (bid - c_off[bx]) + 8 * bx;
    int ry0 = bx * 8;

    float inv = g_inv;
    float nb  = g_nb;

    // ---- weighted, lane-duplicated distance table: 2 entries/thread ----
    #pragma unroll
    for (int e = tid; e < 512; e += 256) {
        int r  = e >> 7;                               // row-pair 0..3
        int m  = e & 127;
        int dx = m - 63;                               // ix - jx
        int dy0 = jy - (ry0 + r);
        int dy1 = dy0 - 4;
        float w0 = (dy0 > 0) ? 2.0f : (dy0 == 0 ? 1.0f : 0.0f);
        float w1 = (dy1 > 0) ? 2.0f : (dy1 == 0 ? 1.0f : 0.0f);
        float d0 = w0 * sqrtf((float)(dy0 * dy0 + dx * dx));
        float d1 = w1 * sqrtf((float)(dy1 * dy1 + dx * dx));
        s_d4[e] = make_float4(d0, d0, d1, d1);
    }

    // ---- normalized f of the full j row (coalesced from batch-major) ----
    #pragma unroll
    for (int e = tid; e < 512; e += 256) {
        int b = e >> 6, x = e & 63;
        s_fj[x * 8 + b] = fmaf(g_a[b * NPIX + jy * 64 + x], inv, nb);
    }

    // ---- this thread's two pixels from the pixel-major mirror ----
    int iA = bx * 512 + tid;
    unsigned long long fA[4], fB[4];
    {
        float4 lo  = *(const float4*)&g_t[iA * 8];
        float4 hi  = *(const float4*)&g_t[iA * 8 + 4];
        float4 lo2 = *(const float4*)&g_t[(iA + 256) * 8];
        float4 hi2 = *(const float4*)&g_t[(iA + 256) * 8 + 4];
        fA[0] = pk2(fmaf(lo.x,  inv, nb), fmaf(lo.y,  inv, nb));
        fA[1] = pk2(fmaf(lo.z,  inv, nb), fmaf(lo.w,  inv, nb));
        fA[2] = pk2(fmaf(hi.x,  inv, nb), fmaf(hi.y,  inv, nb));
        fA[3] = pk2(fmaf(hi.z,  inv, nb), fmaf(hi.w,  inv, nb));
        fB[0] = pk2(fmaf(lo2.x, inv, nb), fmaf(lo2.y, inv, nb));
        fB[1] = pk2(fmaf(lo2.z, inv, nb), fmaf(lo2.w, inv, nb));
        fB[2] = pk2(fmaf(hi2.x, inv, nb), fmaf(hi2.y, inv, nb));
        fB[3] = pk2(fmaf(hi2.z, inv, nb), fmaf(hi2.w, inv, nb));
    }
    __syncthreads();

    int ix = tid & 63;
    // row-pair table for local row r = tid>>6; signed index m = ix - jj + 63
    const ulonglong2* dbase =
        (const ulonglong2*)(s_d4 + ((tid >> 6) << 7) + (ix + 63));

    unsigned long long acc0 = 0ull, acc1 = 0ull;       // A and B chains
    #pragma unroll 16
    for (int jj = 0; jj < 64; jj++) {
        ulonglong2 ja = *(const ulonglong2*)(s_fj + jj * 8);      // b 0..3
        ulonglong2 jb = *(const ulonglong2*)(s_fj + jj * 8 + 4);  // b 4..7
        ulonglong2 d2 = dbase[-jj];                     // (d0,d0),(d1,d1) LDS.128

        unsigned long long p = mul2(fA[0], ja.x);       // lanes: even/odd batches
        p = fma2(fA[1], ja.y, p);
        p = fma2(fA[2], jb.x, p);
        p = fma2(fA[3], jb.y, p);
        acc0 = fma2(p, d2.x, acc0);

        unsigned long long q = mul2(fB[0], ja.x);
        q = fma2(fB[1], ja.y, q);
        q = fma2(fB[2], jb.x, q);
        q = fma2(fB[3], jb.y, q);
        acc1 = fma2(q, d2.y, acc1);
    }

    float a0, a1, b0, b1;
    unpk2(acc0, a0, a1);
    unpk2(acc1, b0, b1);
    double dacc = ((double)a0 + (double)a1) + ((double)b0 + (double)b1);
    #pragma unroll
    for (int o = 16; o; o >>= 1)
        dacc += __shfl_xor_sync(0xffffffffu, dacc, o);
    if (lane == 0) s_red[wid] = dacc;
    __syncthreads();
    if (tid == 0) {
        double s = s_red[0];
        #pragma unroll
        for (int w = 1; w < 8; w++) s += s_red[w];
        g_part[bid] = s;
        __threadfence();
        s_last = (atomicAdd(&g_cnt_main, 1u) == (MAIN_BLKS - 1u));
    }
    __syncthreads();

    // ---- last block reduces all partials (fixed order -> deterministic) ----
    if (s_last) {
        double s = 0.0;
        for (int k = tid; k < MAIN_BLKS; k += 256)
            s += ((volatile double*)g_part)[k];
        #pragma unroll
        for (int o = 16; o; o >>= 1)
            s += __shfl_xor_sync(0xffffffffu, s, o);
        if (lane == 0) s_red[wid] = s;
        __syncthreads();
        if (tid == 0) {
            double t = s_red[0];
            #pragma unroll
            for (int w = 1; w < 8; w++) t += s_red[w];
            out[0] = (float)(t / 134217728.0);          // / (B*N*N)
            g_cnt_main = 0;                             // reset for graph replay
        }
    }
}

extern "C" void kernel_launch(void* const* d_in, const int* in_sizes, int n_in,
                              void* d_out, int out_size) {
    const float4* in4 = (const float4*)d_in[0];
    float*        out = (float*)d_out;

    k_pre<<<PRE_BLKS, 128>>>(in4);
    k_main<<<MAIN_BLKS, 256>>>(out);
}

// round 12
// speedup vs baseline: 1.0644x; 1.0152x over previous
#include <cuda_runtime.h>
#include <math.h>

// Problem: input (8, 64, 64, 3) fp32 -> scalar fp32.
#define NB   8
#define NPIX 4096            // 64*64
#define NELE (NB * NPIX)     // 32768
#define PRE_BLKS 64
#define MAIN_BLKS 288        // triangular block set (see c_off)

// ---- scratch (no allocations allowed -> __device__ globals) ----
__device__ __align__(16) float g_a[NELE];        // |x|.sum(-1), layout [b][i]
__device__ __align__(16) float g_t[NELE];        // same values, pixel-major [i][b]
__device__ float        g_bmin[PRE_BLKS];
__device__ float        g_bmax[PRE_BLKS];
__device__ float        g_inv, g_nb;             // f = fma(a, inv, nb)
__device__ double       g_part[MAIN_BLKS];
__device__ unsigned int g_cnt_pre  = 0;          // self-resetting counters
__device__ unsigned int g_cnt_main = 0;

// i-tile = 8 rows (bx 0..7). For each bx, jy in [8bx, 64) -> 64-8bx blocks.
__constant__ int c_off[9] = {0, 64, 120, 168, 208, 240, 264, 280, 288};

// ---- packed f32x2 helpers (Blackwell FFMA2 — only reachable via PTX) ----
__device__ __forceinline__ unsigned long long pk2(float lo, float hi) {
    unsigned long long r;
    asm("mov.b64 %0, {%1,%2};" : "=l"(r) : "f"(lo), "f"(hi));
    return r;
}
__device__ __forceinline__ void unpk2(unsigned long long v, float& lo, float& hi) {
    asm("mov.b64 {%0,%1}, %2;" : "=f"(lo), "=f"(hi) : "l"(v));
}
__device__ __forceinline__ unsigned long long mul2(unsigned long long a, unsigned long long b) {
    unsigned long long r;
    asm("mul.rn.f32x2 %0, %1, %2;" : "=l"(r) : "l"(a), "l"(b));
    return r;
}
__device__ __forceinline__ unsigned long long fma2(unsigned long long a, unsigned long long b,
                                                   unsigned long long c) {
    unsigned long long r;
    asm("fma.rn.f32x2 %0, %1, %2, %3;" : "=l"(r) : "l"(a), "l"(b), "l"(c));
    return r;
}

// ---------------------------------------------------------------
// 4 pixels/thread (3 x LDG.128). Writes g_a (batch-major), g_t (pixel-major),
// per-block min/max; last block finishes min/max and publishes (inv, nb).
__global__ void __launch_bounds__(128) k_pre(const float4* __restrict__ in4) {
    int t = blockIdx.x * 128 + threadIdx.x;            // 0..8191
    float4 a = in4[t * 3 + 0];
    float4 b = in4[t * 3 + 1];
    float4 c = in4[t * 3 + 2];

    float4 s;
    s.x = fabsf(a.x) + fabsf(a.y) + fabsf(a.z);
    s.y = fabsf(a.w) + fabsf(b.x) + fabsf(b.y);
    s.z = fabsf(b.z) + fabsf(b.w) + fabsf(c.x);
    s.w = fabsf(c.y) + fabsf(c.z) + fabsf(c.w);
    *(float4*)&g_a[t * 4] = s;

    int bb = t >> 10;                                  // batch
    int p0 = (t & 1023) * 4;                           // first pixel
    g_t[(p0 + 0) * 8 + bb] = s.x;
    g_t[(p0 + 1) * 8 + bb] = s.y;
    g_t[(p0 + 2) * 8 + bb] = s.z;
    g_t[(p0 + 3) * 8 + bb] = s.w;

    float mn = fminf(fminf(s.x, s.y), fminf(s.z, s.w));
    float mx = fmaxf(fmaxf(s.x, s.y), fmaxf(s.z, s.w));
    #pragma unroll
    for (int o = 16; o; o >>= 1) {
        mn = fminf(mn, __shfl_xor_sync(0xffffffffu, mn, o));
        mx = fmaxf(mx, __shfl_xor_sync(0xffffffffu, mx, o));
    }
    __shared__ float smn[4], smx[4];
    __shared__ bool  s_last;
    int wid = threadIdx.x >> 5, lid = threadIdx.x & 31;
    if (lid == 0) { smn[wid] = mn; smx[wid] = mx; }
    __syncthreads();
    if (threadIdx.x == 0) {
        #pragma unroll
        for (int w = 1; w < 4; w++) { mn = fminf(mn, smn[w]); mx = fmaxf(mx, smx[w]); }
        g_bmin[blockIdx.x] = mn;
        g_bmax[blockIdx.x] = mx;
        __threadfence();
        s_last = (atomicAdd(&g_cnt_pre, 1u) == PRE_BLKS - 1u);
    }
    __syncthreads();
    if (s_last) {
        if (threadIdx.x < 64) {
            float m2 = ((volatile float*)g_bmin)[threadIdx.x];
            float x2 = ((volatile float*)g_bmax)[threadIdx.x];
            #pragma unroll
            for (int o = 16; o; o >>= 1) {
                m2 = fminf(m2, __shfl_xor_sync(0xffffffffu, m2, o));
                x2 = fmaxf(x2, __shfl_xor_sync(0xffffffffu, x2, o));
            }
            if (threadIdx.x == 0)  { smn[0] = m2; smx[1] = x2; }
            if (threadIdx.x == 32) { smx[0] = x2; smn[1] = m2; }
        }
        __syncthreads();
        if (threadIdx.x == 0) {
            float mnF = fminf(smn[0], smn[1]);
            float mxF = fmaxf(smx[0], smx[1]);
            float inv = 1.0f / (mxF - mnF);
            g_inv = inv;
            g_nb  = -mnF * inv;
            g_cnt_pre = 0;                              // reset for graph replay
        }
    }
}

// ---------------------------------------------------------------
// Symmetric main kernel. Block = (i-tile of 8 rows = 512 px) x (full j-row).
// Only jy >= ry0 launched; pair weight {0,1,2} folded into the lane-duplicated
// signed-index distance table s_d4[r][ix - jx + 63] = (d0,d0,d1,d1) for local
// rows r and r+4. Thread: iA = tile+tid (row r = tid>>6), iB = iA+256 (r+4).
//
// KEY RESTRUCTURE: Sum_j d_ij (f_i . f_j) = f_i . (Sum_j d_ij f_j) = f_i . T_i.
// Inner loop accumulates T (8 independent FMA2 chains, no serial dependency);
// the f_i dot happens once after the loop, and the f_i global loads (600cyc)
// are issued before the loop and consumed only after it.
__global__ void __launch_bounds__(256) k_main(float* __restrict__ out) {
    __shared__ __align__(16) float4 s_d4[512];         // [r 0..3][m 0..127]
    __shared__ __align__(16) float  s_fj[512];         // 64 j x 8 b, pixel-major
    __shared__ double s_red[8];
    __shared__ bool   s_last;

    int tid  = threadIdx.x;
    int lane = tid & 31, wid = tid >> 5;

    // ---- decode (bx, jy) ----
    int bid = blockIdx.x;
    int bx = 0;
    #pragma unroll
    for (int t = 1; t < 8; t++) bx += (bid >= c_off[t]);
    int jy  = (bid - c_off[bx]) + 8 * bx;
    int ry0 = bx * 8;

    float inv = g_inv;
    float nb  = g_nb;

    // ---- issue this thread's two pixel loads EARLY (consumed post-loop) ----
    int iA = bx * 512 + tid;
    float4 pA_lo = *(const float4*)&g_t[iA * 8];
    float4 pA_hi = *(const float4*)&g_t[iA * 8 + 4];
    float4 pB_lo = *(const float4*)&g_t[(iA + 256) * 8];
    float4 pB_hi = *(const float4*)&g_t[(iA + 256) * 8 + 4];

    // ---- weighted, lane-duplicated distance table: 2 entries/thread ----
    #pragma unroll
    for (int e = tid; e < 512; e += 256) {
        int r  = e >> 7;                               // row-pair 0..3
        int m  = e & 127;
        int dx = m - 63;                               // ix - jx
        int dy0 = jy - (ry0 + r);
        int dy1 = dy0 - 4;
        float w0 = (dy0 > 0) ? 2.0f : (dy0 == 0 ? 1.0f : 0.0f);
        float w1 = (dy1 > 0) ? 2.0f : (dy1 == 0 ? 1.0f : 0.0f);
        float d0 = w0 * sqrtf((float)(dy0 * dy0 + dx * dx));
        float d1 = w1 * sqrtf((float)(dy1 * dy1 + dx * dx));
        s_d4[e] = make_float4(d0, d0, d1, d1);
    }

    // ---- normalized f of the full j row (coalesced from batch-major) ----
    #pragma unroll
    for (int e = tid; e < 512; e += 256) {
        int b = e >> 6, x = e & 63;
        s_fj[x * 8 + b] = fmaf(g_a[b * NPIX + jy * 64 + x], inv, nb);
    }
    __syncthreads();

    int ix = tid & 63;
    // row-pair table for local row r = tid>>6; signed index m = ix - jj + 63
    const ulonglong2* dbase =
        (const ulonglong2*)(s_d4 + ((tid >> 6) << 7) + (ix + 63));

    // ---- T accumulation: 8 independent FMA2 chains ----
    unsigned long long TA0 = 0ull, TA1 = 0ull, TA2 = 0ull, TA3 = 0ull;
    unsigned long long TB0 = 0ull, TB1 = 0ull, TB2 = 0ull, TB3 = 0ull;
    #pragma unroll 16
    for (int jj = 0; jj < 64; jj++) {
        ulonglong2 ja = *(const ulonglong2*)(s_fj + jj * 8);      // b 0..3
        ulonglong2 jb = *(const ulonglong2*)(s_fj + jj * 8 + 4);  // b 4..7
        ulonglong2 d2 = dbase[-jj];                     // (d0,d0),(d1,d1) LDS.128

        TA0 = fma2(d2.x, ja.x, TA0);
        TA1 = fma2(d2.x, ja.y, TA1);
        TA2 = fma2(d2.x, jb.x, TA2);
        TA3 = fma2(d2.x, jb.y, TA3);
        TB0 = fma2(d2.y, ja.x, TB0);
        TB1 = fma2(d2.y, ja.y, TB1);
        TB2 = fma2(d2.y, jb.x, TB2);
        TB3 = fma2(d2.y, jb.y, TB3);
    }

    // ---- post-loop: normalize pixels, dot with T ----
    unsigned long long fA0 = pk2(fmaf(pA_lo.x, inv, nb), fmaf(pA_lo.y, inv, nb));
    unsigned long long fA1 = pk2(fmaf(pA_lo.z, inv, nb), fmaf(pA_lo.w, inv, nb));
    unsigned long long fA2 = pk2(fmaf(pA_hi.x, inv, nb), fmaf(pA_hi.y, inv, nb));
    unsigned long long fA3 = pk2(fmaf(pA_hi.z, inv, nb), fmaf(pA_hi.w, inv, nb));
    unsigned long long fB0 = pk2(fmaf(pB_lo.x, inv, nb), fmaf(pB_lo.y, inv, nb));
    unsigned long long fB1 = pk2(fmaf(pB_lo.z, inv, nb), fmaf(pB_lo.w, inv, nb));
    unsigned long long fB2 = pk2(fmaf(pB_hi.x, inv, nb), fmaf(pB_hi.y, inv, nb));
    unsigned long long fB3 = pk2(fmaf(pB_hi.z, inv, nb), fmaf(pB_hi.w, inv, nb));

    unsigned long long rA = mul2(fA0, TA0);
    rA = fma2(fA1, TA1, rA);
    rA = fma2(fA2, TA2, rA);
    rA = fma2(fA3, TA3, rA);
    unsigned long long rB = mul2(fB0, TB0);
    rB = fma2(fB1, TB1, rB);
    rB = fma2(fB2, TB2, rB);
    rB = fma2(fB3, TB3, rB);

    float a0, a1, b0, b1;
    unpk2(rA, a0, a1);
    unpk2(rB, b0, b1);
    double dacc = ((double)a0 + (double)a1) + ((double)b0 + (double)b1);
    #pragma unroll
    for (int o = 16; o; o >>= 1)
        dacc += __shfl_xor_sync(0xffffffffu, dacc, o);
    if (lane == 0) s_red[wid] = dacc;
    __syncthreads();
    if (tid == 0) {
        double s = s_red[0];
        #pragma unroll
        for (int w = 1; w < 8; w++) s += s_red[w];
        g_part[bid] = s;
        __threadfence();
        s_last = (atomicAdd(&g_cnt_main, 1u) == (MAIN_BLKS - 1u));
    }
    __syncthreads();

    // ---- last block reduces all partials (fixed order -> deterministic) ----
    if (s_last) {
        double s = 0.0;
        for (int k = tid; k < MAIN_BLKS; k += 256)
            s += ((volatile double*)g_part)[k];
        #pragma unroll
        for (int o = 16; o; o >>= 1)
            s += __shfl_xor_sync(0xffffffffu, s, o);
        if (lane == 0) s_red[wid] = s;
        __syncthreads();
        if (tid == 0) {
            double t = s_red[0];
            #pragma unroll
            for (int w = 1; w < 8; w++) t += s_red[w];
            out[0] = (float)(t / 134217728.0);          // / (B*N*N)
            g_cnt_main = 0;                             // reset for graph replay
        }
    }
}

extern "C" void kernel_launch(void* const* d_in, const int* in_sizes, int n_in,
                              void* d_out, int out_size) {
    const float4* in4 = (const float4*)d_in[0];
    float*        out = (float*)d_out;

    k_pre<<<PRE_BLKS, 128>>>(in4);
    k_main<<<MAIN_BLKS, 256>>>(out);
}

// round 13
// speedup vs baseline: 1.2138x; 1.1404x over previous
#include <cuda_runtime.h>
#include <math.h>

// Problem: input (8, 64, 64, 3) fp32 -> scalar fp32.
#define NB   8
#define NPIX 4096            // 64*64
#define NELE (NB * NPIX)     // 32768
#define PRE_BLKS 64
#define MAIN_BLKS 288        // triangular block set (see c_off)

// ---- scratch (no allocations allowed -> __device__ globals) ----
__device__ __align__(16) float g_a[NELE];        // |x|.sum(-1), layout [b][i]
__device__ __align__(16) float g_t[NELE];        // same values, pixel-major [i][b]
__device__ unsigned int g_minbits = 0x7F800000u; // +inf (a >= 0 -> uint order ok)
__device__ unsigned int g_maxbits = 0u;
__device__ double       g_part[MAIN_BLKS];
__device__ unsigned int g_cnt_main = 0;          // self-resetting counter

// i-tile = 8 rows (bx 0..7). For each bx, jy in [8bx, 64) -> 64-8bx blocks.
__constant__ int c_off[9] = {0, 64, 120, 168, 208, 240, 264, 280, 288};

// ---- packed f32x2 helpers (Blackwell FFMA2 — only reachable via PTX) ----
__device__ __forceinline__ unsigned long long pk2(float lo, float hi) {
    unsigned long long r;
    asm("mov.b64 %0, {%1,%2};" : "=l"(r) : "f"(lo), "f"(hi));
    return r;
}
__device__ __forceinline__ void unpk2(unsigned long long v, float& lo, float& hi) {
    asm("mov.b64 {%0,%1}, %2;" : "=f"(lo), "=f"(hi) : "l"(v));
}
__device__ __forceinline__ unsigned long long mul2(unsigned long long a, unsigned long long b) {
    unsigned long long r;
    asm("mul.rn.f32x2 %0, %1, %2;" : "=l"(r) : "l"(a), "l"(b));
    return r;
}
__device__ __forceinline__ unsigned long long fma2(unsigned long long a, unsigned long long b,
                                                   unsigned long long c) {
    unsigned long long r;
    asm("fma.rn.f32x2 %0, %1, %2, %3;" : "=l"(r) : "l"(a), "l"(b), "l"(c));
    return r;
}

// ---------------------------------------------------------------
// 4 pixels/thread (3 x LDG.128). Writes g_a (batch-major), g_t (pixel-major);
// global min/max via two uint-bit atomics per block (single phase).
__global__ void __launch_bounds__(128) k_pre(const float4* __restrict__ in4) {
    int t = blockIdx.x * 128 + threadIdx.x;            // 0..8191
    float4 a = in4[t * 3 + 0];
    float4 b = in4[t * 3 + 1];
    float4 c = in4[t * 3 + 2];

    float4 s;
    s.x = fabsf(a.x) + fabsf(a.y) + fabsf(a.z);
    s.y = fabsf(a.w) + fabsf(b.x) + fabsf(b.y);
    s.z = fabsf(b.z) + fabsf(b.w) + fabsf(c.x);
    s.w = fabsf(c.y) + fabsf(c.z) + fabsf(c.w);
    *(float4*)&g_a[t * 4] = s;

    int bb = t >> 10;                                  // batch
    int p0 = (t & 1023) * 4;                           // first pixel
    g_t[(p0 + 0) * 8 + bb] = s.x;
    g_t[(p0 + 1) * 8 + bb] = s.y;
    g_t[(p0 + 2) * 8 + bb] = s.z;
    g_t[(p0 + 3) * 8 + bb] = s.w;

    float mn = fminf(fminf(s.x, s.y), fminf(s.z, s.w));
    float mx = fmaxf(fmaxf(s.x, s.y), fmaxf(s.z, s.w));
    #pragma unroll
    for (int o = 16; o; o >>= 1) {
        mn = fminf(mn, __shfl_xor_sync(0xffffffffu, mn, o));
        mx = fmaxf(mx, __shfl_xor_sync(0xffffffffu, mx, o));
    }
    __shared__ float smn[4], smx[4];
    int wid = threadIdx.x >> 5, lid = threadIdx.x & 31;
    if (lid == 0) { smn[wid] = mn; smx[wid] = mx; }
    __syncthreads();
    if (threadIdx.x == 0) {
        #pragma unroll
        for (int w = 1; w < 4; w++) { mn = fminf(mn, smn[w]); mx = fmaxf(mx, smx[w]); }
        atomicMin(&g_minbits, __float_as_uint(mn));
        atomicMax(&g_maxbits, __float_as_uint(mx));
    }
}

// ---------------------------------------------------------------
// Symmetric main kernel (R8 inner loop, empirically fastest). Launched with
// PDL: the data-independent distance table (incl. 512 MUFU sqrts/block) is
// built BEFORE griddepcontrol.wait, overlapping k_pre's execution.
// Block = (i-tile of 8 rows = 512 px) x (full j-row of 64). Pair weight
// {0,1,2} folded into s_d2[r][ix-jx+63]; thread: iA=tile+tid (row r=tid>>6),
// iB=iA+256 (row r+4).
__global__ void __launch_bounds__(256) k_main(float* __restrict__ out) {
    __shared__ __align__(8)  float2 s_d2[512];         // [r 0..3][m 0..127]
    __shared__ __align__(16) float  s_fj[512];         // 64 j x 8 b, pixel-major
    __shared__ double s_red[8];
    __shared__ bool   s_last;

    int tid  = threadIdx.x;
    int lane = tid & 31, wid = tid >> 5;

    // ---- decode (bx, jy) ----
    int bid = blockIdx.x;
    int bx = 0;
    #pragma unroll
    for (int t = 1; t < 8; t++) bx += (bid >= c_off[t]);
    int jy  = (bid - c_off[bx]) + 8 * bx;
    int ry0 = bx * 8;

    // ---- DATA-INDEPENDENT: weighted signed-index distance table ----
    #pragma unroll
    for (int e = tid; e < 512; e += 256) {
        int r  = e >> 7;                               // row-pair 0..3
        int m  = e & 127;
        int dx = m - 63;                               // ix - jx
        int dy0 = jy - (ry0 + r);
        int dy1 = dy0 - 4;
        float w0 = (dy0 > 0) ? 2.0f : (dy0 == 0 ? 1.0f : 0.0f);
        float w1 = (dy1 > 0) ? 2.0f : (dy1 == 0 ? 1.0f : 0.0f);
        float2 d;
        d.x = w0 * sqrtf((float)(dy0 * dy0 + dx * dx));
        d.y = w1 * sqrtf((float)(dy1 * dy1 + dx * dx));
        s_d2[e] = d;
    }

    // ---- wait for k_pre's writes (PDL sync; no-op if serialized) ----
    asm volatile("griddepcontrol.wait;" ::: "memory");

    float mn  = __uint_as_float(g_minbits);
    float mx  = __uint_as_float(g_maxbits);
    float inv = 1.0f / (mx - mn);
    float nb  = -mn * inv;                              // f = fma(a, inv, nb)

    // ---- normalized f of the full j row (coalesced from batch-major) ----
    #pragma unroll
    for (int e = tid; e < 512; e += 256) {
        int b = e >> 6, x = e & 63;
        s_fj[x * 8 + b] = fmaf(g_a[b * NPIX + jy * 64 + x], inv, nb);
    }

    // ---- this thread's two pixels from the pixel-major mirror ----
    int iA = bx * 512 + tid;
    int iB = iA + 256;
    unsigned long long fA[4], fB[4];
    {
        float4 lo  = *(const float4*)&g_t[iA * 8];
        float4 hi  = *(const float4*)&g_t[iA * 8 + 4];
        float4 lo2 = *(const float4*)&g_t[iB * 8];
        float4 hi2 = *(const float4*)&g_t[iB * 8 + 4];
        fA[0] = pk2(fmaf(lo.x,  inv, nb), fmaf(lo.y,  inv, nb));
        fA[1] = pk2(fmaf(lo.z,  inv, nb), fmaf(lo.w,  inv, nb));
        fA[2] = pk2(fmaf(hi.x,  inv, nb), fmaf(hi.y,  inv, nb));
        fA[3] = pk2(fmaf(hi.z,  inv, nb), fmaf(hi.w,  inv, nb));
        fB[0] = pk2(fmaf(lo2.x, inv, nb), fmaf(lo2.y, inv, nb));
        fB[1] = pk2(fmaf(lo2.z, inv, nb), fmaf(lo2.w, inv, nb));
        fB[2] = pk2(fmaf(hi2.x, inv, nb), fmaf(hi2.y, inv, nb));
        fB[3] = pk2(fmaf(hi2.z, inv, nb), fmaf(hi2.w, inv, nb));
    }
    __syncthreads();

    int ix = tid & 63;
    // row-pair table for local row r = tid>>6; signed index m = ix - jj + 63
    const float2* dbase = s_d2 + ((tid >> 6) << 7) + (ix + 63);

    unsigned long long acc0 = 0ull, acc1 = 0ull;       // A and B chains
    #pragma unroll 16
    for (int jj = 0; jj < 64; jj++) {
        ulonglong2 ja = *(const ulonglong2*)(s_fj + jj * 8);      // b 0..3
        ulonglong2 jb = *(const ulonglong2*)(s_fj + jj * 8 + 4);  // b 4..7
        float2 d = dbase[-jj];                          // one LDS.64, imm offset

        unsigned long long p = mul2(fA[0], ja.x);       // lanes: even/odd batches
        p = fma2(fA[1], ja.y, p);
        p = fma2(fA[2], jb.x, p);
        p = fma2(fA[3], jb.y, p);
        acc0 = fma2(p, pk2(d.x, d.x), acc0);

        unsigned long long q = mul2(fB[0], ja.x);
        q = fma2(fB[1], ja.y, q);
        q = fma2(fB[2], jb.x, q);
        q = fma2(fB[3], jb.y, q);
        acc1 = fma2(q, pk2(d.y, d.y), acc1);
    }

    float a0, a1, b0, b1;
    unpk2(acc0, a0, a1);
    unpk2(acc1, b0, b1);
    double dacc = ((double)a0 + (double)a1) + ((double)b0 + (double)b1);
    #pragma unroll
    for (int o = 16; o; o >>= 1)
        dacc += __shfl_xor_sync(0xffffffffu, dacc, o);
    if (lane == 0) s_red[wid] = dacc;
    __syncthreads();
    if (tid == 0) {
        double s = s_red[0];
        #pragma unroll
        for (int w = 1; w < 8; w++) s += s_red[w];
        g_part[bid] = s;
        __threadfence();
        s_last = (atomicAdd(&g_cnt_main, 1u) == (MAIN_BLKS - 1u));
    }
    __syncthreads();

    // ---- last block reduces all partials (fixed order -> deterministic) ----
    if (s_last) {
        double s = 0.0;
        for (int k = tid; k < MAIN_BLKS; k += 256)
            s += ((volatile double*)g_part)[k];
        #pragma unroll
        for (int o = 16; o; o >>= 1)
            s += __shfl_xor_sync(0xffffffffu, s, o);
        if (lane == 0) s_red[wid] = s;
        __syncthreads();
        if (tid == 0) {
            double t = s_red[0];
            #pragma unroll
            for (int w = 1; w < 8; w++) t += s_red[w];
            out[0] = (float)(t / 134217728.0);          // / (B*N*N)
            g_cnt_main = 0;                             // reset for graph replay
            g_minbits  = 0x7F800000u;
            g_maxbits  = 0u;
        }
    }
}

extern "C" void kernel_launch(void* const* d_in, const int* in_sizes, int n_in,
                              void* d_out, int out_size) {
    const float4* in4 = (const float4*)d_in[0];
    float*        out = (float*)d_out;

    k_pre<<<PRE_BLKS, 128>>>(in4);

    // k_main with programmatic dependent launch: its distance-table prologue
    // overlaps k_pre; griddepcontrol.wait gates the data-dependent part.
    cudaLaunchConfig_t cfg = {};
    cfg.gridDim  = dim3(MAIN_BLKS);
    cfg.blockDim = dim3(256);
    cudaLaunchAttribute attr[1];
    attr[0].id = cudaLaunchAttributeProgrammaticStreamSerialization;
    attr[0].val.programmaticStreamSerializationAllowed = 1;
    cfg.attrs    = attr;
    cfg.numAttrs = 1;
    cudaLaunchKernelEx(&cfg, k_main, out);
}